// round 1
// baseline (speedup 1.0000x reference)
#include <cuda_runtime.h>
#include <math.h>

#define B_    8
#define L_    4106
#define C_    768
#define VPT   10
#define NH    12
#define HD    64
#define WS    14
#define NWIN  25
#define BW    200          // B_*NWIN
#define LW    206          // VPT + WS*WS
#define BH    2400         // BW*NH
#define MX    32848        // B_*L_
#define MQ    41200        // BW*LW
#define SCALE 0.125f

// ---------------- scratch (static, allocation-free) ----------------
__device__ float g_xn [25227264];   // LN1 out; later LN2 out
__device__ float g_tok[31641600];   // tok; later attn@v (reassembled)
__device__ float g_qkv[94924800];   // qkv
__device__ float g_attn[101846400]; // attn; later MLP hidden (needs 100909056)
__device__ float g_proj[31641600];
__device__ float g_x2 [25227264];

// ---------------- LayerNorm (one block per row of 768) ----------------
__global__ void __launch_bounds__(256) ln_kernel(const float* __restrict__ x,
        const float* __restrict__ w, const float* __restrict__ b,
        float* __restrict__ out)
{
    int row = blockIdx.x, t = threadIdx.x;
    const float* xr = x + (size_t)row * C_;
    float v0 = xr[t], v1 = xr[t + 256], v2 = xr[t + 512];
    float s  = v0 + v1 + v2;
    float s2 = v0 * v0 + v1 * v1 + v2 * v2;
    __shared__ float r1[8], r2[8];
    #pragma unroll
    for (int o = 16; o > 0; o >>= 1) {
        s  += __shfl_xor_sync(0xffffffffu, s,  o);
        s2 += __shfl_xor_sync(0xffffffffu, s2, o);
    }
    if ((t & 31) == 0) { r1[t >> 5] = s; r2[t >> 5] = s2; }
    __syncthreads();
    float S = 0.f, S2 = 0.f;
    #pragma unroll
    for (int wi = 0; wi < 8; wi++) { S += r1[wi]; S2 += r2[wi]; }
    float mean = S * (1.f / C_);
    float var  = S2 * (1.f / C_) - mean * mean;
    float rstd = rsqrtf(var + 1e-5f);
    float* orow = out + (size_t)row * C_;
    orow[t]       = (v0 - mean) * rstd * w[t]       + b[t];
    orow[t + 256] = (v1 - mean) * rstd * w[t + 256] + b[t + 256];
    orow[t + 512] = (v2 - mean) * rstd * w[t + 512] + b[t + 512];
}

// ---------------- build tok (200,206,768) ----------------
__global__ void gather_tok(const float* __restrict__ xn, float* __restrict__ tok)
{
    size_t idx = (size_t)blockIdx.x * 256 + threadIdx.x;
    if (idx >= (size_t)BW * LW * C_) return;
    int c = (int)(idx % C_);
    int rest = (int)(idx / C_);
    int l = rest % LW;
    int bw = rest / LW;
    float val = 0.f;
    if (l < VPT) {
        int b = bw & 7;                          // prompt ordering: (nwin, B) -> bw % B
        val = xn[((size_t)b * L_ + l) * C_ + c];
    } else {
        int r = l - VPT;
        int i = r / WS, j = r % WS;
        int b = bw / NWIN, w = bw % NWIN;        // window ordering: (B, nwin)
        int h  = (w / 5) * WS + i;
        int wc = (w % 5) * WS + j;
        if (h < 64 && wc < 64)
            val = xn[((size_t)b * L_ + VPT + h * 64 + wc) * C_ + c];
    }
    tok[idx] = val;
}

// ---------------- big SGEMM: C = A(MxK) * B(NxK)^T + bias, epilogue modes ----------------
// MODE 0: +bias   MODE 1: +bias,gelu   MODE 2: +bias,+res
__device__ __forceinline__ float gelu_f(float v) {
    return 0.5f * v * (1.0f + erff(v * 0.70710678118654752f));
}

template<int MODE>
__global__ void __launch_bounds__(256) gemm_nt(const float* __restrict__ A,
        const float* __restrict__ Bm, const float* __restrict__ bias,
        const float* __restrict__ res, float* __restrict__ Cm,
        int M, int N, int K)
{
    __shared__ float As[8][128];
    __shared__ float Bs[8][128];
    int t = threadIdx.x;
    int m0 = blockIdx.y * 128;
    int n0 = blockIdx.x * 128;
    int tx = t & 15, ty = t >> 4;
    float acc[8][8];
    #pragma unroll
    for (int i = 0; i < 8; i++)
        #pragma unroll
        for (int j = 0; j < 8; j++) acc[i][j] = 0.f;

    int lr = t >> 1;
    int lk = (t & 1) * 4;
    const float* Aptr = A  + (size_t)(m0 + lr) * K + lk;
    const float* Bptr = Bm + (size_t)(n0 + lr) * K + lk;
    bool aval = (m0 + lr) < M;                    // N always multiple of 128 here
    float4 z4 = make_float4(0.f, 0.f, 0.f, 0.f);
    float4 a4 = aval ? *(const float4*)Aptr : z4;
    float4 b4 = *(const float4*)Bptr;

    for (int kb = 0; kb < K; kb += 8) {
        As[lk + 0][lr] = a4.x; As[lk + 1][lr] = a4.y;
        As[lk + 2][lr] = a4.z; As[lk + 3][lr] = a4.w;
        Bs[lk + 0][lr] = b4.x; Bs[lk + 1][lr] = b4.y;
        Bs[lk + 2][lr] = b4.z; Bs[lk + 3][lr] = b4.w;
        __syncthreads();
        if (kb + 8 < K) {
            a4 = aval ? *(const float4*)(Aptr + kb + 8) : z4;
            b4 = *(const float4*)(Bptr + kb + 8);
        }
        #pragma unroll
        for (int kk = 0; kk < 8; kk++) {
            float4 a0 = *(const float4*)&As[kk][ty * 8];
            float4 a1 = *(const float4*)&As[kk][ty * 8 + 4];
            float4 b0 = *(const float4*)&Bs[kk][tx * 8];
            float4 b1 = *(const float4*)&Bs[kk][tx * 8 + 4];
            float av_[8] = {a0.x, a0.y, a0.z, a0.w, a1.x, a1.y, a1.z, a1.w};
            float bv_[8] = {b0.x, b0.y, b0.z, b0.w, b1.x, b1.y, b1.z, b1.w};
            #pragma unroll
            for (int i = 0; i < 8; i++)
                #pragma unroll
                for (int j = 0; j < 8; j++)
                    acc[i][j] += av_[i] * bv_[j];
        }
        __syncthreads();
    }

    #pragma unroll
    for (int i = 0; i < 8; i++) {
        int m = m0 + ty * 8 + i;
        if (m >= M) continue;
        #pragma unroll
        for (int j = 0; j < 8; j++) {
            int n = n0 + tx * 8 + j;
            float v = acc[i][j] + bias[n];
            if (MODE == 1) v = gelu_f(v);
            if (MODE == 2) v += res[(size_t)m * N + n];
            Cm[(size_t)m * N + n] = v;
        }
    }
}

// ---------------- batched q*SCALE @ k^T (reads strided qkv) ----------------
__global__ void __launch_bounds__(256) qk_kernel(const float* __restrict__ qkv,
                                                 float* __restrict__ attn)
{
    int bh = blockIdx.z;
    int bw = bh / NH, hh = bh % NH;
    int m0 = blockIdx.y * 64, n0 = blockIdx.x * 64;
    const float* qb = qkv + (size_t)bw * LW * 2304 + hh * HD;
    const float* kb = qb + 768;
    __shared__ float Qs[16][64];
    __shared__ float Ks[16][64];
    int t = threadIdx.x;
    int tx = t & 15, ty = t >> 4;
    int lr  = t >> 2;
    int lk4 = (t & 3) * 4;
    float acc[4][4];
    #pragma unroll
    for (int i = 0; i < 4; i++)
        #pragma unroll
        for (int j = 0; j < 4; j++) acc[i][j] = 0.f;
    float4 z4 = make_float4(0.f, 0.f, 0.f, 0.f);

    for (int k0 = 0; k0 < HD; k0 += 16) {
        int qm = m0 + lr, kn = n0 + lr;
        float4 qa = (qm < LW) ? *(const float4*)(qb + (size_t)qm * 2304 + k0 + lk4) : z4;
        float4 ka = (kn < LW) ? *(const float4*)(kb + (size_t)kn * 2304 + k0 + lk4) : z4;
        Qs[lk4 + 0][lr] = qa.x * SCALE; Qs[lk4 + 1][lr] = qa.y * SCALE;
        Qs[lk4 + 2][lr] = qa.z * SCALE; Qs[lk4 + 3][lr] = qa.w * SCALE;
        Ks[lk4 + 0][lr] = ka.x; Ks[lk4 + 1][lr] = ka.y;
        Ks[lk4 + 2][lr] = ka.z; Ks[lk4 + 3][lr] = ka.w;
        __syncthreads();
        #pragma unroll
        for (int kk = 0; kk < 16; kk++) {
            float4 a = *(const float4*)&Qs[kk][ty * 4];
            float4 b = *(const float4*)&Ks[kk][tx * 4];
            float av_[4] = {a.x, a.y, a.z, a.w};
            float bv_[4] = {b.x, b.y, b.z, b.w};
            #pragma unroll
            for (int i = 0; i < 4; i++)
                #pragma unroll
                for (int j = 0; j < 4; j++)
                    acc[i][j] += av_[i] * bv_[j];
        }
        __syncthreads();
    }
    #pragma unroll
    for (int i = 0; i < 4; i++) {
        int m = m0 + ty * 4 + i;
        if (m >= LW) continue;
        #pragma unroll
        for (int j = 0; j < 4; j++) {
            int n = n0 + tx * 4 + j;
            if (n < LW)
                attn[(size_t)bh * LW * LW + (size_t)m * LW + n] = acc[i][j];
        }
    }
}

// ---------------- fused rel-pos add + softmax (one block per attn row) ----------------
__global__ void __launch_bounds__(256) softmax_kernel(float* __restrict__ attn,
        const float* __restrict__ qkv, const float* __restrict__ rph,
        const float* __restrict__ rpw)
{
    int row = blockIdx.x;                 // 0 .. BH*LW-1
    int bh = row / LW, r = row % LW;
    int t = threadIdx.x;
    __shared__ float sq[64];
    __shared__ float srel[28];
    __shared__ float redm[8], reds[8];
    float* arow = attn + (size_t)bh * LW * LW + (size_t)r * LW;
    bool dorel = (r >= VPT);

    if (dorel) {
        int rr = r - VPT;
        int qi = rr / WS, qj = rr % WS;
        const float* qrow = qkv + (size_t)(bh / NH) * LW * 2304 + (size_t)r * 2304 + (bh % NH) * HD;
        if (t < 64) sq[t] = qrow[t];
        __syncthreads();
        if (t < 224) {
            int p = t >> 3, e = t & 7;
            int dir = p / 14, kk = p % 14;
            const float* rp = dir ? (rpw + (qj - kk + 13) * HD)
                                  : (rph + (qi - kk + 13) * HD);
            float s = 0.f;
            #pragma unroll
            for (int d = 0; d < 8; d++) s += sq[e * 8 + d] * rp[e * 8 + d];
            s += __shfl_down_sync(0xffffffffu, s, 4);
            s += __shfl_down_sync(0xffffffffu, s, 2);
            s += __shfl_down_sync(0xffffffffu, s, 1);
            if (e == 0) srel[p] = s;
        }
    }
    __syncthreads();

    float v = -1e30f;
    if (t < LW) {
        v = arow[t];
        if (dorel && t >= VPT) {
            int cc = t - VPT;
            v += srel[cc / 14] + srel[14 + cc % 14];
        }
    }
    // block max
    float m = v;
    #pragma unroll
    for (int o = 16; o > 0; o >>= 1) m = fmaxf(m, __shfl_xor_sync(0xffffffffu, m, o));
    if ((t & 31) == 0) redm[t >> 5] = m;
    __syncthreads();
    m = redm[0];
    #pragma unroll
    for (int wi = 1; wi < 8; wi++) m = fmaxf(m, redm[wi]);

    float e = (t < LW) ? __expf(v - m) : 0.f;
    float s = e;
    #pragma unroll
    for (int o = 16; o > 0; o >>= 1) s += __shfl_xor_sync(0xffffffffu, s, o);
    if ((t & 31) == 0) reds[t >> 5] = s;
    __syncthreads();
    s = 0.f;
    #pragma unroll
    for (int wi = 0; wi < 8; wi++) s += reds[wi];

    if (t < LW) arow[t] = e / s;
}

// ---------------- batched attn @ v, reassembled to (Bw,Lw,C) ----------------
__global__ void __launch_bounds__(256) av_kernel(const float* __restrict__ attn,
        const float* __restrict__ qkv, float* __restrict__ av)
{
    int bh = blockIdx.y;
    int m0 = blockIdx.x * 32;
    int bw = bh / NH, hh = bh % NH;
    const float* vb = qkv + (size_t)bw * LW * 2304 + hh * HD + 1536;
    const float* ab = attn + (size_t)bh * LW * LW;
    __shared__ float As[32][33];
    __shared__ float Vs[32][64];
    int t = threadIdx.x;
    int ar = t >> 3, ac = (t & 7) * 4;
    int vr = t >> 3, vc = (t & 7) * 8;
    int ty = t >> 5, tx = t & 31;
    float acc[4][2] = {{0.f,0.f},{0.f,0.f},{0.f,0.f},{0.f,0.f}};

    for (int l0 = 0; l0 < LW; l0 += 32) {
        int m = m0 + ar;
        #pragma unroll
        for (int u = 0; u < 4; u++) {
            int l = l0 + ac + u;
            As[ar][ac + u] = (m < LW && l < LW) ? ab[(size_t)m * LW + l] : 0.f;
        }
        int lv = l0 + vr;
        if (lv < LW) {
            float4 v0 = *(const float4*)(vb + (size_t)lv * 2304 + vc);
            float4 v1 = *(const float4*)(vb + (size_t)lv * 2304 + vc + 4);
            *(float4*)&Vs[vr][vc]     = v0;
            *(float4*)&Vs[vr][vc + 4] = v1;
        } else {
            float4 z4 = make_float4(0.f, 0.f, 0.f, 0.f);
            *(float4*)&Vs[vr][vc]     = z4;
            *(float4*)&Vs[vr][vc + 4] = z4;
        }
        __syncthreads();
        #pragma unroll
        for (int kk = 0; kk < 32; kk++) {
            float b0 = Vs[kk][tx], b1 = Vs[kk][tx + 32];
            #pragma unroll
            for (int u = 0; u < 4; u++) {
                float a = As[ty + u * 8][kk];
                acc[u][0] += a * b0;
                acc[u][1] += a * b1;
            }
        }
        __syncthreads();
    }
    #pragma unroll
    for (int u = 0; u < 4; u++) {
        int m = m0 + ty + u * 8;
        if (m < LW) {
            float* o = av + ((size_t)bw * LW + m) * C_ + hh * HD;
            o[tx]      = acc[u][0];
            o[tx + 32] = acc[u][1];
        }
    }
}

// ---------------- un-window + prompt-mean + residual ----------------
__global__ void combine_kernel(const float* __restrict__ x,
        const float* __restrict__ proj, float* __restrict__ x2)
{
    size_t idx = (size_t)blockIdx.x * 256 + threadIdx.x;
    if (idx >= (size_t)B_ * L_ * C_) return;
    int c = (int)(idx % C_);
    int rest = (int)(idx / C_);
    int tt = rest % L_;
    int b = rest / L_;
    float val;
    if (tt < VPT) {
        float s = 0.f;
        #pragma unroll
        for (int w = 0; w < NWIN; w++)
            s += proj[((size_t)(w * B_ + b) * LW + tt) * C_ + c];
        val = s * (1.f / NWIN);
    } else {
        int sp = tt - VPT;
        int h = sp >> 6, wc = sp & 63;
        int wh = h / WS,  i2 = h % WS;
        int ww = wc / WS, j2 = wc % WS;
        int bw = b * NWIN + wh * 5 + ww;
        int l  = VPT + i2 * WS + j2;
        val = proj[((size_t)bw * LW + l) * C_ + c];
    }
    x2[idx] = x[idx] + val;
}

// ---------------- launch ----------------
extern "C" void kernel_launch(void* const* d_in, const int* in_sizes, int n_in,
                              void* d_out, int out_size)
{
    const float* x      = (const float*)d_in[0];
    const float* ln1_w  = (const float*)d_in[1];
    const float* ln1_b  = (const float*)d_in[2];
    const float* qkv_w  = (const float*)d_in[3];
    const float* qkv_b  = (const float*)d_in[4];
    const float* proj_w = (const float*)d_in[5];
    const float* proj_b = (const float*)d_in[6];
    const float* rph    = (const float*)d_in[7];
    const float* rpw    = (const float*)d_in[8];
    const float* ln2_w  = (const float*)d_in[9];
    const float* ln2_b  = (const float*)d_in[10];
    const float* mlp_w1 = (const float*)d_in[11];
    const float* mlp_b1 = (const float*)d_in[12];
    const float* mlp_w2 = (const float*)d_in[13];
    const float* mlp_b2 = (const float*)d_in[14];
    float* out = (float*)d_out;

    float *xn, *tok, *qkv, *attn, *proj, *x2;
    cudaGetSymbolAddress((void**)&xn,   g_xn);
    cudaGetSymbolAddress((void**)&tok,  g_tok);
    cudaGetSymbolAddress((void**)&qkv,  g_qkv);
    cudaGetSymbolAddress((void**)&attn, g_attn);
    cudaGetSymbolAddress((void**)&proj, g_proj);
    cudaGetSymbolAddress((void**)&x2,   g_x2);

    // 1) LN1
    ln_kernel<<<MX, 256>>>(x, ln1_w, ln1_b, xn);
    // 2) tok gather
    gather_tok<<<(int)(((size_t)BW * LW * C_ + 255) / 256), 256>>>(xn, tok);
    // 3) qkv = tok @ qkv_w^T + b
    gemm_nt<0><<<dim3(2304 / 128, (MQ + 127) / 128), 256>>>(tok, qkv_w, qkv_b, nullptr, qkv, MQ, 2304, 768);
    // 4) attn = q*scale @ k^T
    qk_kernel<<<dim3(4, 4, BH), 256>>>(qkv, attn);
    // 5) rel-pos + softmax
    softmax_kernel<<<BH * LW, 256>>>(attn, qkv, rph, rpw);
    // 6) attn @ v -> (Bw,Lw,C) into tok buffer
    av_kernel<<<dim3(7, BH), 256>>>(attn, qkv, tok);
    // 7) proj
    gemm_nt<0><<<dim3(768 / 128, (MQ + 127) / 128), 256>>>(tok, proj_w, proj_b, nullptr, proj, MQ, 768, 768);
    // 8) un-window + residual
    combine_kernel<<<(int)(((size_t)B_ * L_ * C_ + 255) / 256), 256>>>(x, proj, x2);
    // 9) LN2
    ln_kernel<<<MX, 256>>>(x2, ln2_w, ln2_b, xn);
    // 10) MLP fc1 + gelu (hidden reuses attn buffer)
    gemm_nt<1><<<dim3(3072 / 128, (MX + 127) / 128), 256>>>(xn, mlp_w1, mlp_b1, nullptr, attn, MX, 3072, 768);
    // 11) MLP fc2 + residual -> out
    gemm_nt<2><<<dim3(768 / 128, (MX + 127) / 128), 256>>>(attn, mlp_w2, mlp_b2, x2, out, MX, 768, 3072);
}

// round 2
// speedup vs baseline: 1.7389x; 1.7389x over previous
#include <cuda_runtime.h>
#include <math.h>

#define B_    8
#define L_    4106
#define C_    768
#define VPT   10
#define NH    12
#define HD    64
#define WS    14
#define NWIN  25
#define BW    200          // B_*NWIN
#define LW    206          // VPT + WS*WS
#define BH    2400         // BW*NH
#define MX    32848        // B_*L_
#define MQ    41200        // BW*LW
#define SCALE 0.125f

// ---------------- scratch (static, allocation-free) ----------------
__device__ float g_xn [25227264];   // LN1 out; later LN2 out
__device__ float g_tok[31641600];   // tok; later attn@v (reassembled)
__device__ float g_qkv[94924800];   // qkv
__device__ float g_attn[101846400]; // attn; later MLP hidden (needs 100909056)
__device__ float g_proj[31641600];
__device__ float g_x2 [25227264];

// ---------------- LayerNorm (one block per row of 768) ----------------
__global__ void __launch_bounds__(256) ln_kernel(const float* __restrict__ x,
        const float* __restrict__ w, const float* __restrict__ b,
        float* __restrict__ out)
{
    int row = blockIdx.x, t = threadIdx.x;
    const float* xr = x + (size_t)row * C_;
    float v0 = xr[t], v1 = xr[t + 256], v2 = xr[t + 512];
    float s  = v0 + v1 + v2;
    float s2 = v0 * v0 + v1 * v1 + v2 * v2;
    __shared__ float r1[8], r2[8];
    #pragma unroll
    for (int o = 16; o > 0; o >>= 1) {
        s  += __shfl_xor_sync(0xffffffffu, s,  o);
        s2 += __shfl_xor_sync(0xffffffffu, s2, o);
    }
    if ((t & 31) == 0) { r1[t >> 5] = s; r2[t >> 5] = s2; }
    __syncthreads();
    float S = 0.f, S2 = 0.f;
    #pragma unroll
    for (int wi = 0; wi < 8; wi++) { S += r1[wi]; S2 += r2[wi]; }
    float mean = S * (1.f / C_);
    float var  = S2 * (1.f / C_) - mean * mean;
    float rstd = rsqrtf(var + 1e-5f);
    float* orow = out + (size_t)row * C_;
    orow[t]       = (v0 - mean) * rstd * w[t]       + b[t];
    orow[t + 256] = (v1 - mean) * rstd * w[t + 256] + b[t + 256];
    orow[t + 512] = (v2 - mean) * rstd * w[t + 512] + b[t + 512];
}

// ---------------- build tok (200,206,768) ----------------
__global__ void gather_tok(const float* __restrict__ xn, float* __restrict__ tok)
{
    size_t idx = (size_t)blockIdx.x * 256 + threadIdx.x;
    if (idx >= (size_t)BW * LW * C_) return;
    int c = (int)(idx % C_);
    int rest = (int)(idx / C_);
    int l = rest % LW;
    int bw = rest / LW;
    float val = 0.f;
    if (l < VPT) {
        int b = bw & 7;                          // prompt ordering: (nwin, B) -> bw % B
        val = xn[((size_t)b * L_ + l) * C_ + c];
    } else {
        int r = l - VPT;
        int i = r / WS, j = r % WS;
        int b = bw / NWIN, w = bw % NWIN;        // window ordering: (B, nwin)
        int h  = (w / 5) * WS + i;
        int wc = (w % 5) * WS + j;
        if (h < 64 && wc < 64)
            val = xn[((size_t)b * L_ + VPT + h * 64 + wc) * C_ + c];
    }
    tok[idx] = val;
}

// ---------------- tf32 tensor-core GEMM: C = A(MxK) @ B(NxK)^T + bias ----------------
// MODE 0: +bias   MODE 1: +bias,gelu   MODE 2: +bias,+res
__device__ __forceinline__ float gelu_f(float v) {
    return 0.5f * v * (1.0f + erff(v * 0.70710678118654752f));
}

__device__ __forceinline__ unsigned f2tf32(float f) {
    unsigned u;
    asm("cvt.rna.tf32.f32 %0, %1;" : "=r"(u) : "f"(f));
    return u;
}

// permute k within each group of 8 so that (c, c+4) become adjacent
__device__ __forceinline__ int kperm(int kk) {
    return (kk & 8) | ((kk & 3) << 1) | ((kk >> 2) & 1);
}

#define SAP 18  // padded smem row stride (floats)

template<int MODE>
__global__ void __launch_bounds__(256) gemm_tf32(const float* __restrict__ A,
        const float* __restrict__ Bm, const float* __restrict__ bias,
        const float* __restrict__ res, float* __restrict__ Cm,
        int M, int N, int K)
{
    __shared__ unsigned As[128 * SAP];
    __shared__ unsigned Bs[128 * SAP];
    const int t = threadIdx.x;
    const int m0 = blockIdx.y * 128, n0 = blockIdx.x * 128;
    const int warp = t >> 5, lane = t & 31;
    const int wm = warp >> 2, wn = warp & 3;      // 2 x 4 warp grid
    const int g = lane >> 2, c = lane & 3;

    float acc[4][4][4];
    #pragma unroll
    for (int i = 0; i < 4; i++)
        #pragma unroll
        for (int j = 0; j < 4; j++)
            #pragma unroll
            for (int q = 0; q < 4; q++) acc[i][j][q] = 0.f;

    const int lr = t >> 2;          // 0..63
    const int lk = (t & 3) * 4;     // 0,4,8,12
    const float* Ap0 = A  + (size_t)(m0 + lr) * K + lk;
    const float* Ap1 = A  + (size_t)(m0 + lr + 64) * K + lk;
    const float* Bp0 = Bm + (size_t)(n0 + lr) * K + lk;
    const float* Bp1 = Bm + (size_t)(n0 + lr + 64) * K + lk;
    const bool av0 = (m0 + lr) < M, av1 = (m0 + lr + 64) < M;
    const float4 z4 = make_float4(0.f, 0.f, 0.f, 0.f);
    float4 ra0 = av0 ? *(const float4*)Ap0 : z4;
    float4 ra1 = av1 ? *(const float4*)Ap1 : z4;
    float4 rb0 = *(const float4*)Bp0;
    float4 rb1 = *(const float4*)Bp1;

    const int s0 = lr * SAP, s1 = (lr + 64) * SAP;
    const int p0 = kperm(lk + 0), p1 = kperm(lk + 1);
    const int p2 = kperm(lk + 2), p3 = kperm(lk + 3);

    for (int kb = 0; kb < K; kb += 16) {
        As[s0 + p0] = f2tf32(ra0.x); As[s0 + p1] = f2tf32(ra0.y);
        As[s0 + p2] = f2tf32(ra0.z); As[s0 + p3] = f2tf32(ra0.w);
        As[s1 + p0] = f2tf32(ra1.x); As[s1 + p1] = f2tf32(ra1.y);
        As[s1 + p2] = f2tf32(ra1.z); As[s1 + p3] = f2tf32(ra1.w);
        Bs[s0 + p0] = f2tf32(rb0.x); Bs[s0 + p1] = f2tf32(rb0.y);
        Bs[s0 + p2] = f2tf32(rb0.z); Bs[s0 + p3] = f2tf32(rb0.w);
        Bs[s1 + p0] = f2tf32(rb1.x); Bs[s1 + p1] = f2tf32(rb1.y);
        Bs[s1 + p2] = f2tf32(rb1.z); Bs[s1 + p3] = f2tf32(rb1.w);
        __syncthreads();

        if (kb + 16 < K) {
            ra0 = av0 ? *(const float4*)(Ap0 + kb + 16) : z4;
            ra1 = av1 ? *(const float4*)(Ap1 + kb + 16) : z4;
            rb0 = *(const float4*)(Bp0 + kb + 16);
            rb1 = *(const float4*)(Bp1 + kb + 16);
        }

        #pragma unroll
        for (int ks = 0; ks < 16; ks += 8) {
            unsigned af[4][4];
            unsigned bf[4][2];
            #pragma unroll
            for (int mt = 0; mt < 4; mt++) {
                int base = (wm * 64 + mt * 16 + g) * SAP + ks + 2 * c;
                uint2 lo = *(const uint2*)&As[base];
                uint2 hi = *(const uint2*)&As[base + 8 * SAP];
                af[mt][0] = lo.x; af[mt][2] = lo.y;
                af[mt][1] = hi.x; af[mt][3] = hi.y;
            }
            #pragma unroll
            for (int nt = 0; nt < 4; nt++) {
                int base = (wn * 32 + nt * 8 + g) * SAP + ks + 2 * c;
                uint2 bb = *(const uint2*)&Bs[base];
                bf[nt][0] = bb.x; bf[nt][1] = bb.y;
            }
            #pragma unroll
            for (int mt = 0; mt < 4; mt++)
                #pragma unroll
                for (int nt = 0; nt < 4; nt++) {
                    asm volatile(
                        "mma.sync.aligned.m16n8k8.row.col.f32.tf32.tf32.f32 "
                        "{%0,%1,%2,%3},{%4,%5,%6,%7},{%8,%9},{%0,%1,%2,%3};"
                        : "+f"(acc[mt][nt][0]), "+f"(acc[mt][nt][1]),
                          "+f"(acc[mt][nt][2]), "+f"(acc[mt][nt][3])
                        : "r"(af[mt][0]), "r"(af[mt][1]),
                          "r"(af[mt][2]), "r"(af[mt][3]),
                          "r"(bf[nt][0]), "r"(bf[nt][1]));
                }
        }
        __syncthreads();
    }

    #pragma unroll
    for (int mt = 0; mt < 4; mt++) {
        #pragma unroll
        for (int half = 0; half < 2; half++) {
            int r = m0 + wm * 64 + mt * 16 + g + half * 8;
            if (r >= M) continue;
            #pragma unroll
            for (int nt = 0; nt < 4; nt++) {
                int col = n0 + wn * 32 + nt * 8 + 2 * c;
                float v0 = acc[mt][nt][half * 2 + 0] + bias[col];
                float v1 = acc[mt][nt][half * 2 + 1] + bias[col + 1];
                if (MODE == 1) { v0 = gelu_f(v0); v1 = gelu_f(v1); }
                if (MODE == 2) {
                    v0 += res[(size_t)r * N + col];
                    v1 += res[(size_t)r * N + col + 1];
                }
                float2 o = make_float2(v0, v1);
                *(float2*)&Cm[(size_t)r * N + col] = o;
            }
        }
    }
}

// ---------------- batched q*SCALE @ k^T (reads strided qkv) ----------------
__global__ void __launch_bounds__(256) qk_kernel(const float* __restrict__ qkv,
                                                 float* __restrict__ attn)
{
    int bh = blockIdx.z;
    int bw = bh / NH, hh = bh % NH;
    int m0 = blockIdx.y * 64, n0 = blockIdx.x * 64;
    const float* qb = qkv + (size_t)bw * LW * 2304 + hh * HD;
    const float* kb = qb + 768;
    __shared__ float Qs[16][64];
    __shared__ float Ks[16][64];
    int t = threadIdx.x;
    int tx = t & 15, ty = t >> 4;
    int lr  = t >> 2;
    int lk4 = (t & 3) * 4;
    float acc[4][4];
    #pragma unroll
    for (int i = 0; i < 4; i++)
        #pragma unroll
        for (int j = 0; j < 4; j++) acc[i][j] = 0.f;
    float4 z4 = make_float4(0.f, 0.f, 0.f, 0.f);

    for (int k0 = 0; k0 < HD; k0 += 16) {
        int qm = m0 + lr, kn = n0 + lr;
        float4 qa = (qm < LW) ? *(const float4*)(qb + (size_t)qm * 2304 + k0 + lk4) : z4;
        float4 ka = (kn < LW) ? *(const float4*)(kb + (size_t)kn * 2304 + k0 + lk4) : z4;
        Qs[lk4 + 0][lr] = qa.x * SCALE; Qs[lk4 + 1][lr] = qa.y * SCALE;
        Qs[lk4 + 2][lr] = qa.z * SCALE; Qs[lk4 + 3][lr] = qa.w * SCALE;
        Ks[lk4 + 0][lr] = ka.x; Ks[lk4 + 1][lr] = ka.y;
        Ks[lk4 + 2][lr] = ka.z; Ks[lk4 + 3][lr] = ka.w;
        __syncthreads();
        #pragma unroll
        for (int kk = 0; kk < 16; kk++) {
            float4 a = *(const float4*)&Qs[kk][ty * 4];
            float4 b = *(const float4*)&Ks[kk][tx * 4];
            float av_[4] = {a.x, a.y, a.z, a.w};
            float bv_[4] = {b.x, b.y, b.z, b.w};
            #pragma unroll
            for (int i = 0; i < 4; i++)
                #pragma unroll
                for (int j = 0; j < 4; j++)
                    acc[i][j] += av_[i] * bv_[j];
        }
        __syncthreads();
    }
    #pragma unroll
    for (int i = 0; i < 4; i++) {
        int m = m0 + ty * 4 + i;
        if (m >= LW) continue;
        #pragma unroll
        for (int j = 0; j < 4; j++) {
            int n = n0 + tx * 4 + j;
            if (n < LW)
                attn[(size_t)bh * LW * LW + (size_t)m * LW + n] = acc[i][j];
        }
    }
}

// ---------------- fused rel-pos add + softmax (one block per attn row) ----------------
__global__ void __launch_bounds__(256) softmax_kernel(float* __restrict__ attn,
        const float* __restrict__ qkv, const float* __restrict__ rph,
        const float* __restrict__ rpw)
{
    int row = blockIdx.x;                 // 0 .. BH*LW-1
    int bh = row / LW, r = row % LW;
    int t = threadIdx.x;
    __shared__ float sq[64];
    __shared__ float srel[28];
    __shared__ float redm[8], reds[8];
    float* arow = attn + (size_t)bh * LW * LW + (size_t)r * LW;
    bool dorel = (r >= VPT);

    if (dorel) {
        int rr = r - VPT;
        int qi = rr / WS, qj = rr % WS;
        const float* qrow = qkv + (size_t)(bh / NH) * LW * 2304 + (size_t)r * 2304 + (bh % NH) * HD;
        if (t < 64) sq[t] = qrow[t];
        __syncthreads();
        if (t < 224) {
            int p = t >> 3, e = t & 7;
            int dir = p / 14, kk = p % 14;
            const float* rp = dir ? (rpw + (qj - kk + 13) * HD)
                                  : (rph + (qi - kk + 13) * HD);
            float s = 0.f;
            #pragma unroll
            for (int d = 0; d < 8; d++) s += sq[e * 8 + d] * rp[e * 8 + d];
            s += __shfl_down_sync(0xffffffffu, s, 4);
            s += __shfl_down_sync(0xffffffffu, s, 2);
            s += __shfl_down_sync(0xffffffffu, s, 1);
            if (e == 0) srel[p] = s;
        }
    }
    __syncthreads();

    float v = -1e30f;
    if (t < LW) {
        v = arow[t];
        if (dorel && t >= VPT) {
            int cc = t - VPT;
            v += srel[cc / 14] + srel[14 + cc % 14];
        }
    }
    // block max
    float m = v;
    #pragma unroll
    for (int o = 16; o > 0; o >>= 1) m = fmaxf(m, __shfl_xor_sync(0xffffffffu, m, o));
    if ((t & 31) == 0) redm[t >> 5] = m;
    __syncthreads();
    m = redm[0];
    #pragma unroll
    for (int wi = 1; wi < 8; wi++) m = fmaxf(m, redm[wi]);

    float e = (t < LW) ? __expf(v - m) : 0.f;
    float s = e;
    #pragma unroll
    for (int o = 16; o > 0; o >>= 1) s += __shfl_xor_sync(0xffffffffu, s, o);
    if ((t & 31) == 0) reds[t >> 5] = s;
    __syncthreads();
    s = 0.f;
    #pragma unroll
    for (int wi = 0; wi < 8; wi++) s += reds[wi];

    if (t < LW) arow[t] = e / s;
}

// ---------------- batched attn @ v, reassembled to (Bw,Lw,C) ----------------
__global__ void __launch_bounds__(256) av_kernel(const float* __restrict__ attn,
        const float* __restrict__ qkv, float* __restrict__ av)
{
    int bh = blockIdx.y;
    int m0 = blockIdx.x * 32;
    int bw = bh / NH, hh = bh % NH;
    const float* vb = qkv + (size_t)bw * LW * 2304 + hh * HD + 1536;
    const float* ab = attn + (size_t)bh * LW * LW;
    __shared__ float As[32][33];
    __shared__ float Vs[32][64];
    int t = threadIdx.x;
    int ar = t >> 3, ac = (t & 7) * 4;
    int vr = t >> 3, vc = (t & 7) * 8;
    int ty = t >> 5, tx = t & 31;
    float acc[4][2] = {{0.f,0.f},{0.f,0.f},{0.f,0.f},{0.f,0.f}};

    for (int l0 = 0; l0 < LW; l0 += 32) {
        int m = m0 + ar;
        #pragma unroll
        for (int u = 0; u < 4; u++) {
            int l = l0 + ac + u;
            As[ar][ac + u] = (m < LW && l < LW) ? ab[(size_t)m * LW + l] : 0.f;
        }
        int lv = l0 + vr;
        if (lv < LW) {
            float4 v0 = *(const float4*)(vb + (size_t)lv * 2304 + vc);
            float4 v1 = *(const float4*)(vb + (size_t)lv * 2304 + vc + 4);
            *(float4*)&Vs[vr][vc]     = v0;
            *(float4*)&Vs[vr][vc + 4] = v1;
        } else {
            float4 z4 = make_float4(0.f, 0.f, 0.f, 0.f);
            *(float4*)&Vs[vr][vc]     = z4;
            *(float4*)&Vs[vr][vc + 4] = z4;
        }
        __syncthreads();
        #pragma unroll
        for (int kk = 0; kk < 32; kk++) {
            float b0 = Vs[kk][tx], b1 = Vs[kk][tx + 32];
            #pragma unroll
            for (int u = 0; u < 4; u++) {
                float a = As[ty + u * 8][kk];
                acc[u][0] += a * b0;
                acc[u][1] += a * b1;
            }
        }
        __syncthreads();
    }
    #pragma unroll
    for (int u = 0; u < 4; u++) {
        int m = m0 + ty + u * 8;
        if (m < LW) {
            float* o = av + ((size_t)bw * LW + m) * C_ + hh * HD;
            o[tx]      = acc[u][0];
            o[tx + 32] = acc[u][1];
        }
    }
}

// ---------------- un-window + prompt-mean + residual ----------------
__global__ void combine_kernel(const float* __restrict__ x,
        const float* __restrict__ proj, float* __restrict__ x2)
{
    size_t idx = (size_t)blockIdx.x * 256 + threadIdx.x;
    if (idx >= (size_t)B_ * L_ * C_) return;
    int c = (int)(idx % C_);
    int rest = (int)(idx / C_);
    int tt = rest % L_;
    int b = rest / L_;
    float val;
    if (tt < VPT) {
        float s = 0.f;
        #pragma unroll
        for (int w = 0; w < NWIN; w++)
            s += proj[((size_t)(w * B_ + b) * LW + tt) * C_ + c];
        val = s * (1.f / NWIN);
    } else {
        int sp = tt - VPT;
        int h = sp >> 6, wc = sp & 63;
        int wh = h / WS,  i2 = h % WS;
        int ww = wc / WS, j2 = wc % WS;
        int bw = b * NWIN + wh * 5 + ww;
        int l  = VPT + i2 * WS + j2;
        val = proj[((size_t)bw * LW + l) * C_ + c];
    }
    x2[idx] = x[idx] + val;
}

// ---------------- launch ----------------
extern "C" void kernel_launch(void* const* d_in, const int* in_sizes, int n_in,
                              void* d_out, int out_size)
{
    const float* x      = (const float*)d_in[0];
    const float* ln1_w  = (const float*)d_in[1];
    const float* ln1_b  = (const float*)d_in[2];
    const float* qkv_w  = (const float*)d_in[3];
    const float* qkv_b  = (const float*)d_in[4];
    const float* proj_w = (const float*)d_in[5];
    const float* proj_b = (const float*)d_in[6];
    const float* rph    = (const float*)d_in[7];
    const float* rpw    = (const float*)d_in[8];
    const float* ln2_w  = (const float*)d_in[9];
    const float* ln2_b  = (const float*)d_in[10];
    const float* mlp_w1 = (const float*)d_in[11];
    const float* mlp_b1 = (const float*)d_in[12];
    const float* mlp_w2 = (const float*)d_in[13];
    const float* mlp_b2 = (const float*)d_in[14];
    float* out = (float*)d_out;

    float *xn, *tok, *qkv, *attn, *proj, *x2;
    cudaGetSymbolAddress((void**)&xn,   g_xn);
    cudaGetSymbolAddress((void**)&tok,  g_tok);
    cudaGetSymbolAddress((void**)&qkv,  g_qkv);
    cudaGetSymbolAddress((void**)&attn, g_attn);
    cudaGetSymbolAddress((void**)&proj, g_proj);
    cudaGetSymbolAddress((void**)&x2,   g_x2);

    // 1) LN1
    ln_kernel<<<MX, 256>>>(x, ln1_w, ln1_b, xn);
    // 2) tok gather
    gather_tok<<<(int)(((size_t)BW * LW * C_ + 255) / 256), 256>>>(xn, tok);
    // 3) qkv = tok @ qkv_w^T + b   (tf32 tensor cores)
    gemm_tf32<0><<<dim3(2304 / 128, (MQ + 127) / 128), 256>>>(tok, qkv_w, qkv_b, nullptr, qkv, MQ, 2304, 768);
    // 4) attn = q*scale @ k^T
    qk_kernel<<<dim3(4, 4, BH), 256>>>(qkv, attn);
    // 5) rel-pos + softmax
    softmax_kernel<<<BH * LW, 256>>>(attn, qkv, rph, rpw);
    // 6) attn @ v -> (Bw,Lw,C) into tok buffer
    av_kernel<<<dim3(7, BH), 256>>>(attn, qkv, tok);
    // 7) proj (tf32)
    gemm_tf32<0><<<dim3(768 / 128, (MQ + 127) / 128), 256>>>(tok, proj_w, proj_b, nullptr, proj, MQ, 768, 768);
    // 8) un-window + residual
    combine_kernel<<<(int)(((size_t)B_ * L_ * C_ + 255) / 256), 256>>>(x, proj, x2);
    // 9) LN2
    ln_kernel<<<MX, 256>>>(x2, ln2_w, ln2_b, xn);
    // 10) MLP fc1 + gelu (hidden reuses attn buffer, tf32)
    gemm_tf32<1><<<dim3(3072 / 128, (MX + 127) / 128), 256>>>(xn, mlp_w1, mlp_b1, nullptr, attn, MX, 3072, 768);
    // 11) MLP fc2 + residual -> out (tf32)
    gemm_tf32<2><<<dim3(768 / 128, (MX + 127) / 128), 256>>>(attn, mlp_w2, mlp_b2, x2, out, MX, 768, 3072);
}

// round 3
// speedup vs baseline: 2.5847x; 1.4864x over previous
#include <cuda_runtime.h>
#include <math.h>

#define B_    8
#define L_    4106
#define C_    768
#define VPT   10
#define NH    12
#define HD    64
#define WS    14
#define NWIN  25
#define BW    200          // B_*NWIN
#define LW    206          // VPT + WS*WS
#define BH    2400         // BW*NH
#define MX    32848        // B_*L_
#define MQ    41200        // BW*LW
#define SCALE 0.125f
#define APITCH 208
#define ASLAB  (APITCH*APITCH)   // 43264 per (b,head)

// ---------------- scratch (static, allocation-free) ----------------
__device__ float g_xn [25227264];    // LN1 out; later LN2 out
__device__ float g_tok[31641600];    // tok; later attn@v (reassembled)
__device__ float g_qkv[94924800];    // qkv
__device__ float g_attn[103850000];  // padded attn (2400*43264=103833600 + tail pad); also MLP hidden (needs 100909056)
__device__ float g_proj[31641600];
__device__ float g_x2 [25227264];

__device__ __forceinline__ unsigned f2u(float f) { return __float_as_uint(f); }

// cp.async 16B with zero-fill predicate
#define CPA16(dst_u32, src_ptr, pred) \
    asm volatile("cp.async.cg.shared.global [%0], [%1], 16, %2;" \
                 :: "r"(dst_u32), "l"(src_ptr), "r"((pred) ? 16 : 0))
#define CP_COMMIT() asm volatile("cp.async.commit_group;")
#define CP_WAIT1()  asm volatile("cp.async.wait_group 1;")

#define MMA_TF32(d, a, b) \
    asm volatile("mma.sync.aligned.m16n8k8.row.col.f32.tf32.tf32.f32 " \
        "{%0,%1,%2,%3},{%4,%5,%6,%7},{%8,%9},{%0,%1,%2,%3};" \
        : "+f"(d[0]), "+f"(d[1]), "+f"(d[2]), "+f"(d[3]) \
        : "r"(a[0]), "r"(a[1]), "r"(a[2]), "r"(a[3]), "r"(b[0]), "r"(b[1]))

// ---------------- LayerNorm (one block per row of 768) ----------------
__global__ void __launch_bounds__(256) ln_kernel(const float* __restrict__ x,
        const float* __restrict__ w, const float* __restrict__ b,
        float* __restrict__ out)
{
    int row = blockIdx.x, t = threadIdx.x;
    const float* xr = x + (size_t)row * C_;
    float v0 = xr[t], v1 = xr[t + 256], v2 = xr[t + 512];
    float s  = v0 + v1 + v2;
    float s2 = v0 * v0 + v1 * v1 + v2 * v2;
    __shared__ float r1[8], r2[8];
    #pragma unroll
    for (int o = 16; o > 0; o >>= 1) {
        s  += __shfl_xor_sync(0xffffffffu, s,  o);
        s2 += __shfl_xor_sync(0xffffffffu, s2, o);
    }
    if ((t & 31) == 0) { r1[t >> 5] = s; r2[t >> 5] = s2; }
    __syncthreads();
    float S = 0.f, S2 = 0.f;
    #pragma unroll
    for (int wi = 0; wi < 8; wi++) { S += r1[wi]; S2 += r2[wi]; }
    float mean = S * (1.f / C_);
    float var  = S2 * (1.f / C_) - mean * mean;
    float rstd = rsqrtf(var + 1e-5f);
    float* orow = out + (size_t)row * C_;
    orow[t]       = (v0 - mean) * rstd * w[t]       + b[t];
    orow[t + 256] = (v1 - mean) * rstd * w[t + 256] + b[t + 256];
    orow[t + 512] = (v2 - mean) * rstd * w[t + 512] + b[t + 512];
}

// ---------------- build tok (200,206,768) ----------------
__global__ void gather_tok(const float* __restrict__ xn, float* __restrict__ tok)
{
    size_t idx = (size_t)blockIdx.x * 256 + threadIdx.x;
    if (idx >= (size_t)BW * LW * C_) return;
    int c = (int)(idx % C_);
    int rest = (int)(idx / C_);
    int l = rest % LW;
    int bw = rest / LW;
    float val = 0.f;
    if (l < VPT) {
        int b = bw & 7;                          // prompt ordering: (nwin, B) -> bw % B
        val = xn[((size_t)b * L_ + l) * C_ + c];
    } else {
        int r = l - VPT;
        int i = r / WS, j = r % WS;
        int b = bw / NWIN, w = bw % NWIN;        // window ordering: (B, nwin)
        int h  = (w / 5) * WS + i;
        int wc = (w % 5) * WS + j;
        if (h < 64 && wc < 64)
            val = xn[((size_t)b * L_ + VPT + h * 64 + wc) * C_ + c];
    }
    tok[idx] = val;
}

// ---------------- tf32 tensor-core GEMM with cp.async 2-stage pipeline ----------------
// C = A(MxK) @ B(NxK)^T + bias.  MODE 0: +bias  MODE 1: +bias,gelu  MODE 2: +bias,+res
__device__ __forceinline__ float gelu_f(float v) {
    return 0.5f * v * (1.0f + erff(v * 0.70710678118654752f));
}

#define GSTR 20   // padded smem row stride (words): (20g+c)%32 all-distinct

template<int MODE>
__global__ void __launch_bounds__(256) gemm_tf32(const float* __restrict__ A,
        const float* __restrict__ Bm, const float* __restrict__ bias,
        const float* __restrict__ res, float* __restrict__ Cm,
        int M, int N, int K)
{
    __shared__ __align__(16) unsigned As[2][128 * GSTR];
    __shared__ __align__(16) unsigned Bs[2][128 * GSTR];
    const int t = threadIdx.x;
    const int m0 = blockIdx.y * 128, n0 = blockIdx.x * 128;
    const int warp = t >> 5, lane = t & 31;
    const int wm = warp >> 2, wn = warp & 3;      // 2 x 4 warp grid, warp tile 64x32
    const int g = lane >> 2, c = lane & 3;

    float acc[4][4][4];
    #pragma unroll
    for (int i = 0; i < 4; i++)
        #pragma unroll
        for (int j = 0; j < 4; j++)
            #pragma unroll
            for (int q = 0; q < 4; q++) acc[i][j][q] = 0.f;

    // copy role: rows r0 and r0+64, 16B chunk at kc
    const int r0 = t >> 2;
    const int kc = (t & 3) * 4;
    const int arow0 = m0 + r0, arow1 = m0 + r0 + 64;
    const bool av0 = arow0 < M, av1 = arow1 < M;
    const float* Asrc0 = A + (size_t)(av0 ? arow0 : 0) * K + kc;
    const float* Asrc1 = A + (size_t)(av1 ? arow1 : 0) * K + kc;
    const float* Bsrc0 = Bm + (size_t)(n0 + r0) * K + kc;
    const float* Bsrc1 = Bm + (size_t)(n0 + r0 + 64) * K + kc;
    const unsigned sa = (unsigned)__cvta_generic_to_shared(&As[0][0]) + (r0 * GSTR + kc) * 4;
    const unsigned sb = (unsigned)__cvta_generic_to_shared(&Bs[0][0]) + (r0 * GSTR + kc) * 4;
    const unsigned stg = 128 * GSTR * 4;
    const unsigned half = 64 * GSTR * 4;

    const int NIT = K >> 4;
    // prologue: stages 0,1
    #pragma unroll
    for (int s = 0; s < 2; s++) {
        int kb = s << 4;
        CPA16(sa + s * stg,        Asrc0 + kb, av0);
        CPA16(sa + s * stg + half, Asrc1 + kb, av1);
        CPA16(sb + s * stg,        Bsrc0 + kb, true);
        CPA16(sb + s * stg + half, Bsrc1 + kb, true);
        CP_COMMIT();
    }

    for (int it = 0; it < NIT; it++) {
        CP_WAIT1();
        __syncthreads();
        const unsigned* as = As[it & 1];
        const unsigned* bs = Bs[it & 1];
        #pragma unroll
        for (int ks = 0; ks < 16; ks += 8) {
            unsigned af[4][4], bf[4][2];
            #pragma unroll
            for (int mt = 0; mt < 4; mt++) {
                int base = (wm * 64 + mt * 16 + g) * GSTR + ks + c;
                af[mt][0] = as[base];
                af[mt][1] = as[base + 8 * GSTR];
                af[mt][2] = as[base + 4];
                af[mt][3] = as[base + 8 * GSTR + 4];
            }
            #pragma unroll
            for (int nt = 0; nt < 4; nt++) {
                int base = (wn * 32 + nt * 8 + g) * GSTR + ks + c;
                bf[nt][0] = bs[base];
                bf[nt][1] = bs[base + 4];
            }
            #pragma unroll
            for (int mt = 0; mt < 4; mt++)
                #pragma unroll
                for (int nt = 0; nt < 4; nt++)
                    MMA_TF32(acc[mt][nt], af[mt], bf[nt]);
        }
        __syncthreads();
        if (it + 2 < NIT) {
            int kb = (it + 2) << 4;
            unsigned so = (it & 1) * stg;
            CPA16(sa + so,        Asrc0 + kb, av0);
            CPA16(sa + so + half, Asrc1 + kb, av1);
            CPA16(sb + so,        Bsrc0 + kb, true);
            CPA16(sb + so + half, Bsrc1 + kb, true);
            CP_COMMIT();
        }
    }

    #pragma unroll
    for (int mt = 0; mt < 4; mt++) {
        #pragma unroll
        for (int hf = 0; hf < 2; hf++) {
            int r = m0 + wm * 64 + mt * 16 + g + hf * 8;
            if (r >= M) continue;
            #pragma unroll
            for (int nt = 0; nt < 4; nt++) {
                int col = n0 + wn * 32 + nt * 8 + 2 * c;
                float v0 = acc[mt][nt][hf * 2 + 0] + bias[col];
                float v1 = acc[mt][nt][hf * 2 + 1] + bias[col + 1];
                if (MODE == 1) { v0 = gelu_f(v0); v1 = gelu_f(v1); }
                if (MODE == 2) {
                    v0 += res[(size_t)r * N + col];
                    v1 += res[(size_t)r * N + col + 1];
                }
                *(float2*)&Cm[(size_t)r * N + col] = make_float2(v0, v1);
            }
        }
    }
}

// ---------------- qk: attn = q*SCALE @ k^T via tf32 mma ----------------
#define QSTR 36   // (36g+c)%32 = (4g+c)%32 all-distinct

__global__ void __launch_bounds__(256) qk_mma(const float* __restrict__ qkv,
                                              float* __restrict__ attn)
{
    int bh = blockIdx.z;
    int bw = bh / NH, hh = bh % NH;
    int m0 = blockIdx.y * 128, n0 = blockIdx.x * 128;
    const float* qb = qkv + (size_t)bw * LW * 2304 + hh * HD;
    const float* kb_ = qb + 768;
    __shared__ __align__(16) unsigned Qs[128 * QSTR];
    __shared__ __align__(16) unsigned Ks[128 * QSTR];
    int t = threadIdx.x;
    int warp = t >> 5, lane = t & 31;
    int wm = warp >> 2, wn = warp & 3;
    int g = lane >> 2, c = lane & 3;
    float acc[4][4][4];
    #pragma unroll
    for (int i = 0; i < 4; i++)
        #pragma unroll
        for (int j = 0; j < 4; j++)
            #pragma unroll
            for (int q = 0; q < 4; q++) acc[i][j][q] = 0.f;

    #pragma unroll
    for (int k0 = 0; k0 < 64; k0 += 32) {
        if (k0) __syncthreads();
        #pragma unroll
        for (int q4 = 0; q4 < 4; q4++) {
            int id = t + q4 * 256;
            int row = id >> 3, lc = (id & 7) * 4;
            float4 qa = make_float4(0.f, 0.f, 0.f, 0.f), ka = qa;
            if (m0 + row < LW) qa = *(const float4*)(qb + (size_t)(m0 + row) * 2304 + k0 + lc);
            if (n0 + row < LW) ka = *(const float4*)(kb_ + (size_t)(n0 + row) * 2304 + k0 + lc);
            unsigned* qd = &Qs[row * QSTR + lc];
            qd[0] = f2u(qa.x * SCALE); qd[1] = f2u(qa.y * SCALE);
            qd[2] = f2u(qa.z * SCALE); qd[3] = f2u(qa.w * SCALE);
            unsigned* kd = &Ks[row * QSTR + lc];
            kd[0] = f2u(ka.x); kd[1] = f2u(ka.y); kd[2] = f2u(ka.z); kd[3] = f2u(ka.w);
        }
        __syncthreads();
        #pragma unroll
        for (int ks = 0; ks < 32; ks += 8) {
            unsigned af[4][4], bf[4][2];
            #pragma unroll
            for (int mt = 0; mt < 4; mt++) {
                int base = (wm * 64 + mt * 16 + g) * QSTR + ks + c;
                af[mt][0] = Qs[base];
                af[mt][1] = Qs[base + 8 * QSTR];
                af[mt][2] = Qs[base + 4];
                af[mt][3] = Qs[base + 8 * QSTR + 4];
            }
            #pragma unroll
            for (int nt = 0; nt < 4; nt++) {
                int base = (wn * 32 + nt * 8 + g) * QSTR + ks + c;
                bf[nt][0] = Ks[base];
                bf[nt][1] = Ks[base + 4];
            }
            #pragma unroll
            for (int mt = 0; mt < 4; mt++)
                #pragma unroll
                for (int nt = 0; nt < 4; nt++)
                    MMA_TF32(acc[mt][nt], af[mt], bf[nt]);
        }
    }

    float* ao = attn + (size_t)bh * ASLAB;
    #pragma unroll
    for (int mt = 0; mt < 4; mt++) {
        #pragma unroll
        for (int hf = 0; hf < 2; hf++) {
            int r = m0 + wm * 64 + mt * 16 + g + hf * 8;
            if (r >= LW) continue;
            #pragma unroll
            for (int nt = 0; nt < 4; nt++) {
                int col = n0 + wn * 32 + nt * 8 + 2 * c;
                if (col < APITCH)
                    *(float2*)&ao[(size_t)r * APITCH + col] =
                        make_float2(acc[mt][nt][hf * 2], acc[mt][nt][hf * 2 + 1]);
            }
        }
    }
}

// ---------------- fused rel-pos add + softmax (one block per attn row) ----------------
__global__ void __launch_bounds__(256) softmax_kernel(float* __restrict__ attn,
        const float* __restrict__ qkv, const float* __restrict__ rph,
        const float* __restrict__ rpw)
{
    int row = blockIdx.x;                 // 0 .. BH*LW-1
    int bh = row / LW, r = row % LW;
    int t = threadIdx.x;
    __shared__ float sq[64];
    __shared__ float srel[28];
    __shared__ float redm[8], reds[8];
    float* arow = attn + (size_t)bh * ASLAB + (size_t)r * APITCH;
    bool dorel = (r >= VPT);

    if (dorel) {
        int rr = r - VPT;
        int qi = rr / WS, qj = rr % WS;
        const float* qrow = qkv + (size_t)(bh / NH) * LW * 2304 + (size_t)r * 2304 + (bh % NH) * HD;
        if (t < 64) sq[t] = qrow[t];
        __syncthreads();
        if (t < 224) {
            int p = t >> 3, e = t & 7;
            int dir = p / 14, kk = p % 14;
            const float* rp = dir ? (rpw + (qj - kk + 13) * HD)
                                  : (rph + (qi - kk + 13) * HD);
            float s = 0.f;
            #pragma unroll
            for (int d = 0; d < 8; d++) s += sq[e * 8 + d] * rp[e * 8 + d];
            s += __shfl_down_sync(0xffffffffu, s, 4);
            s += __shfl_down_sync(0xffffffffu, s, 2);
            s += __shfl_down_sync(0xffffffffu, s, 1);
            if (e == 0) srel[p] = s;
        }
    }
    __syncthreads();

    float v = -1e30f;
    if (t < LW) {
        v = arow[t];
        if (dorel && t >= VPT) {
            int cc = t - VPT;
            v += srel[cc / 14] + srel[14 + cc % 14];
        }
    }
    float m = v;
    #pragma unroll
    for (int o = 16; o > 0; o >>= 1) m = fmaxf(m, __shfl_xor_sync(0xffffffffu, m, o));
    if ((t & 31) == 0) redm[t >> 5] = m;
    __syncthreads();
    m = redm[0];
    #pragma unroll
    for (int wi = 1; wi < 8; wi++) m = fmaxf(m, redm[wi]);

    float e = (t < LW) ? __expf(v - m) : 0.f;
    float s = e;
    #pragma unroll
    for (int o = 16; o > 0; o >>= 1) s += __shfl_xor_sync(0xffffffffu, s, o);
    if ((t & 31) == 0) reds[t >> 5] = s;
    __syncthreads();
    s = 0.f;
    #pragma unroll
    for (int wi = 0; wi < 8; wi++) s += reds[wi];

    if (t < APITCH) arow[t] = e / s;      // cols 206,207 get exact 0
}

// ---------------- av: P(206x206,pitch208) @ V(206x64) via tf32 mma ----------------
#define VSTR 20

__global__ void __launch_bounds__(256) av_mma(const float* __restrict__ attn,
        const float* __restrict__ qkv, float* __restrict__ av)
{
    int bh = blockIdx.y;
    int m0 = blockIdx.x * 128;
    int bw = bh / NH, hh = bh % NH;
    const float* vb = qkv + (size_t)bw * LW * 2304 + hh * HD + 1536;
    const float* ab = attn + (size_t)bh * ASLAB;
    __shared__ __align__(16) unsigned Ps[128 * VSTR];
    __shared__ __align__(16) unsigned Vs[64 * VSTR];
    int t = threadIdx.x;
    int warp = t >> 5, lane = t & 31;
    int wm = warp >> 2, wn = warp & 3;     // warp tile 64x16
    int g = lane >> 2, c = lane & 3;
    float acc[4][2][4];
    #pragma unroll
    for (int i = 0; i < 4; i++)
        #pragma unroll
        for (int j = 0; j < 2; j++)
            #pragma unroll
            for (int q = 0; q < 4; q++) acc[i][j][q] = 0.f;

    for (int l0 = 0; l0 < APITCH; l0 += 16) {
        if (l0) __syncthreads();
        #pragma unroll
        for (int q2 = 0; q2 < 2; q2++) {
            int id = t + q2 * 256;
            int row = id >> 2, lc = (id & 3) * 4;
            float4 p = *(const float4*)(ab + (size_t)(m0 + row) * APITCH + l0 + lc);
            unsigned* pd = &Ps[row * VSTR + lc];
            pd[0] = f2u(p.x); pd[1] = f2u(p.y); pd[2] = f2u(p.z); pd[3] = f2u(p.w);
        }
        {
            int l = t >> 4, nc = (t & 15) * 4;
            float4 v = make_float4(0.f, 0.f, 0.f, 0.f);
            if (l0 + l < LW) v = *(const float4*)(vb + (size_t)(l0 + l) * 2304 + nc);
            Vs[(nc + 0) * VSTR + l] = f2u(v.x);
            Vs[(nc + 1) * VSTR + l] = f2u(v.y);
            Vs[(nc + 2) * VSTR + l] = f2u(v.z);
            Vs[(nc + 3) * VSTR + l] = f2u(v.w);
        }
        __syncthreads();
        #pragma unroll
        for (int ks = 0; ks < 16; ks += 8) {
            unsigned af[4][4], bf[2][2];
            #pragma unroll
            for (int mt = 0; mt < 4; mt++) {
                int base = (wm * 64 + mt * 16 + g) * VSTR + ks + c;
                af[mt][0] = Ps[base];
                af[mt][1] = Ps[base + 8 * VSTR];
                af[mt][2] = Ps[base + 4];
                af[mt][3] = Ps[base + 8 * VSTR + 4];
            }
            #pragma unroll
            for (int nt = 0; nt < 2; nt++) {
                int base = (wn * 16 + nt * 8 + g) * VSTR + ks + c;
                bf[nt][0] = Vs[base];
                bf[nt][1] = Vs[base + 4];
            }
            #pragma unroll
            for (int mt = 0; mt < 4; mt++)
                #pragma unroll
                for (int nt = 0; nt < 2; nt++)
                    MMA_TF32(acc[mt][nt], af[mt], bf[nt]);
        }
    }

    #pragma unroll
    for (int mt = 0; mt < 4; mt++) {
        #pragma unroll
        for (int hf = 0; hf < 2; hf++) {
            int m = m0 + wm * 64 + mt * 16 + g + hf * 8;
            if (m >= LW) continue;
            float* o = av + ((size_t)bw * LW + m) * C_ + hh * HD;
            #pragma unroll
            for (int nt = 0; nt < 2; nt++) {
                int col = wn * 16 + nt * 8 + 2 * c;
                *(float2*)&o[col] = make_float2(acc[mt][nt][hf * 2], acc[mt][nt][hf * 2 + 1]);
            }
        }
    }
}

// ---------------- un-window + prompt-mean + residual ----------------
__global__ void combine_kernel(const float* __restrict__ x,
        const float* __restrict__ proj, float* __restrict__ x2)
{
    size_t idx = (size_t)blockIdx.x * 256 + threadIdx.x;
    if (idx >= (size_t)B_ * L_ * C_) return;
    int c = (int)(idx % C_);
    int rest = (int)(idx / C_);
    int tt = rest % L_;
    int b = rest / L_;
    float val;
    if (tt < VPT) {
        float s = 0.f;
        #pragma unroll
        for (int w = 0; w < NWIN; w++)
            s += proj[((size_t)(w * B_ + b) * LW + tt) * C_ + c];
        val = s * (1.f / NWIN);
    } else {
        int sp = tt - VPT;
        int h = sp >> 6, wc = sp & 63;
        int wh = h / WS,  i2 = h % WS;
        int ww = wc / WS, j2 = wc % WS;
        int bw = b * NWIN + wh * 5 + ww;
        int l  = VPT + i2 * WS + j2;
        val = proj[((size_t)bw * LW + l) * C_ + c];
    }
    x2[idx] = x[idx] + val;
}

// ---------------- launch ----------------
extern "C" void kernel_launch(void* const* d_in, const int* in_sizes, int n_in,
                              void* d_out, int out_size)
{
    const float* x      = (const float*)d_in[0];
    const float* ln1_w  = (const float*)d_in[1];
    const float* ln1_b  = (const float*)d_in[2];
    const float* qkv_w  = (const float*)d_in[3];
    const float* qkv_b  = (const float*)d_in[4];
    const float* proj_w = (const float*)d_in[5];
    const float* proj_b = (const float*)d_in[6];
    const float* rph    = (const float*)d_in[7];
    const float* rpw    = (const float*)d_in[8];
    const float* ln2_w  = (const float*)d_in[9];
    const float* ln2_b  = (const float*)d_in[10];
    const float* mlp_w1 = (const float*)d_in[11];
    const float* mlp_b1 = (const float*)d_in[12];
    const float* mlp_w2 = (const float*)d_in[13];
    const float* mlp_b2 = (const float*)d_in[14];
    float* out = (float*)d_out;

    float *xn, *tok, *qkv, *attn, *proj, *x2;
    cudaGetSymbolAddress((void**)&xn,   g_xn);
    cudaGetSymbolAddress((void**)&tok,  g_tok);
    cudaGetSymbolAddress((void**)&qkv,  g_qkv);
    cudaGetSymbolAddress((void**)&attn, g_attn);
    cudaGetSymbolAddress((void**)&proj, g_proj);
    cudaGetSymbolAddress((void**)&x2,   g_x2);

    // 1) LN1
    ln_kernel<<<MX, 256>>>(x, ln1_w, ln1_b, xn);
    // 2) tok gather
    gather_tok<<<(int)(((size_t)BW * LW * C_ + 255) / 256), 256>>>(xn, tok);
    // 3) qkv = tok @ qkv_w^T + b
    gemm_tf32<0><<<dim3(2304 / 128, (MQ + 127) / 128), 256>>>(tok, qkv_w, qkv_b, nullptr, qkv, MQ, 2304, 768);
    // 4) attn = q*scale @ k^T (tensor cores, padded attn)
    qk_mma<<<dim3(2, 2, BH), 256>>>(qkv, attn);
    // 5) rel-pos + softmax (zero-fills pad cols)
    softmax_kernel<<<BH * LW, 256>>>(attn, qkv, rph, rpw);
    // 6) attn @ v -> (Bw,Lw,C) into tok buffer (tensor cores)
    av_mma<<<dim3(2, BH), 256>>>(attn, qkv, tok);
    // 7) proj
    gemm_tf32<0><<<dim3(768 / 128, (MQ + 127) / 128), 256>>>(tok, proj_w, proj_b, nullptr, proj, MQ, 768, 768);
    // 8) un-window + residual
    combine_kernel<<<(int)(((size_t)B_ * L_ * C_ + 255) / 256), 256>>>(x, proj, x2);
    // 9) LN2
    ln_kernel<<<MX, 256>>>(x2, ln2_w, ln2_b, xn);
    // 10) MLP fc1 + gelu (hidden reuses attn buffer)
    gemm_tf32<1><<<dim3(3072 / 128, (MX + 127) / 128), 256>>>(xn, mlp_w1, mlp_b1, nullptr, attn, MX, 3072, 768);
    // 11) MLP fc2 + residual -> out
    gemm_tf32<2><<<dim3(768 / 128, (MX + 127) / 128), 256>>>(attn, mlp_w2, mlp_b2, x2, out, MX, 768, 3072);
}

// round 4
// speedup vs baseline: 2.7393x; 1.0598x over previous
#include <cuda_runtime.h>
#include <math.h>

#define B_    8
#define L_    4106
#define C_    768
#define VPT   10
#define NH    12
#define HD    64
#define WS    14
#define NWIN  25
#define BW    200          // B_*NWIN
#define LW    206          // VPT + WS*WS
#define BH    2400         // BW*NH
#define MX    32848        // B_*L_
#define MQ    41200        // BW*LW
#define SCALE 0.125f
#define APITCH 208
#define ASLAB  (APITCH*APITCH)   // 43264 per (b,head)

// ---------------- scratch (static, allocation-free) ----------------
__device__ float g_xn [25227264];    // LN1 out; later LN2 out
__device__ float g_tok[31641600];    // tok; later attn@v (reassembled)
__device__ float g_qkv[94924800];    // qkv
__device__ float g_attn[103850000];  // padded attn; also MLP hidden
__device__ float g_proj[31641600];
__device__ float g_x2 [25227264];
__device__ float g_w  [7077888];     // RNA-rounded weights: qkv|proj|w1|w2

#define WOFF_QKV  0
#define WOFF_PROJ 1769472
#define WOFF_W1   2359296
#define WOFF_W2   4718592

__device__ __forceinline__ unsigned f2u(float f) { return __float_as_uint(f); }
__device__ __forceinline__ float rna(float f) {
    unsigned u;
    asm("cvt.rna.tf32.f32 %0, %1;" : "=r"(u) : "f"(f));
    return __uint_as_float(u);
}

// cp.async 16B with zero-fill predicate
#define CPA16(dst_u32, src_ptr, pred) \
    asm volatile("cp.async.cg.shared.global [%0], [%1], 16, %2;" \
                 :: "r"(dst_u32), "l"(src_ptr), "r"((pred) ? 16 : 0))
#define CP_COMMIT() asm volatile("cp.async.commit_group;")

#define MMA_TF32(d, a, b) \
    asm volatile("mma.sync.aligned.m16n8k8.row.col.f32.tf32.tf32.f32 " \
        "{%0,%1,%2,%3},{%4,%5,%6,%7},{%8,%9},{%0,%1,%2,%3};" \
        : "+f"(d[0]), "+f"(d[1]), "+f"(d[2]), "+f"(d[3]) \
        : "r"(a[0]), "r"(a[1]), "r"(a[2]), "r"(a[3]), "r"(b[0]), "r"(b[1]))

// ---------------- weight pre-round to tf32 (RNA) ----------------
__global__ void round_w(const float* __restrict__ in, float* __restrict__ out, int n)
{
    int i = blockIdx.x * 256 + threadIdx.x;
    if (i < n) out[i] = rna(in[i]);
}

// ---------------- LayerNorm (one block per row of 768), tf32-rounded out ----------------
__global__ void __launch_bounds__(256) ln_kernel(const float* __restrict__ x,
        const float* __restrict__ w, const float* __restrict__ b,
        float* __restrict__ out)
{
    int row = blockIdx.x, t = threadIdx.x;
    const float* xr = x + (size_t)row * C_;
    float v0 = xr[t], v1 = xr[t + 256], v2 = xr[t + 512];
    float s  = v0 + v1 + v2;
    float s2 = v0 * v0 + v1 * v1 + v2 * v2;
    __shared__ float r1[8], r2[8];
    #pragma unroll
    for (int o = 16; o > 0; o >>= 1) {
        s  += __shfl_xor_sync(0xffffffffu, s,  o);
        s2 += __shfl_xor_sync(0xffffffffu, s2, o);
    }
    if ((t & 31) == 0) { r1[t >> 5] = s; r2[t >> 5] = s2; }
    __syncthreads();
    float S = 0.f, S2 = 0.f;
    #pragma unroll
    for (int wi = 0; wi < 8; wi++) { S += r1[wi]; S2 += r2[wi]; }
    float mean = S * (1.f / C_);
    float var  = S2 * (1.f / C_) - mean * mean;
    float rstd = rsqrtf(var + 1e-5f);
    float* orow = out + (size_t)row * C_;
    orow[t]       = rna((v0 - mean) * rstd * w[t]       + b[t]);
    orow[t + 256] = rna((v1 - mean) * rstd * w[t + 256] + b[t + 256]);
    orow[t + 512] = rna((v2 - mean) * rstd * w[t + 512] + b[t + 512]);
}

// ---------------- build tok (200,206,768) ----------------
__global__ void gather_tok(const float* __restrict__ xn, float* __restrict__ tok)
{
    size_t idx = (size_t)blockIdx.x * 256 + threadIdx.x;
    if (idx >= (size_t)BW * LW * C_) return;
    int c = (int)(idx % C_);
    int rest = (int)(idx / C_);
    int l = rest % LW;
    int bw = rest / LW;
    float val = 0.f;
    if (l < VPT) {
        int b = bw & 7;                          // prompt ordering: (nwin, B) -> bw % B
        val = xn[((size_t)b * L_ + l) * C_ + c];
    } else {
        int r = l - VPT;
        int i = r / WS, j = r % WS;
        int b = bw / NWIN, w = bw % NWIN;        // window ordering: (B, nwin)
        int h  = (w / 5) * WS + i;
        int wc = (w % 5) * WS + j;
        if (h < 64 && wc < 64)
            val = xn[((size_t)b * L_ + VPT + h * 64 + wc) * C_ + c];
    }
    tok[idx] = val;                              // already tf32 from ln
}

// ---------------- tf32 GEMM, 4-stage cp.async, 1 sync/iter ----------------
// C = A(MxK) @ B(NxK)^T + bias.  MODE 0: +bias  MODE 1: +bias,gelu  MODE 2: +bias,+res
// RND: round outputs to tf32 (for tensors consumed by later GEMMs)
__device__ __forceinline__ float gelu_f(float v) {
    return 0.5f * v * (1.0f + erff(v * 0.70710678118654752f));
}

#define GSTR 20   // padded smem row stride (words): (20g+c)%32 all-distinct
#define GSTAGE_W (128 * GSTR)
#define GEMM_SMEM (2 * 4 * GSTAGE_W * 4)

template<int MODE, int RND>
__global__ void __launch_bounds__(256) gemm_tf32(const float* __restrict__ A,
        const float* __restrict__ Bm, const float* __restrict__ bias,
        const float* __restrict__ res, float* __restrict__ Cm,
        int M, int N, int K)
{
    extern __shared__ __align__(16) unsigned smp[];
    unsigned* Asm_ = smp;                  // 4 stages
    unsigned* Bsm_ = smp + 4 * GSTAGE_W;
    const int t = threadIdx.x;
    const int m0 = blockIdx.y * 128, n0 = blockIdx.x * 128;
    const int warp = t >> 5, lane = t & 31;
    const int wm = warp >> 2, wn = warp & 3;      // 2 x 4 warp grid, warp tile 64x32
    const int g = lane >> 2, c = lane & 3;

    float acc[4][4][4];
    #pragma unroll
    for (int i = 0; i < 4; i++)
        #pragma unroll
        for (int j = 0; j < 4; j++)
            #pragma unroll
            for (int q = 0; q < 4; q++) acc[i][j][q] = 0.f;

    const int r0 = t >> 2;
    const int kc = (t & 3) * 4;
    const int arow0 = m0 + r0, arow1 = m0 + r0 + 64;
    const bool av0 = arow0 < M, av1 = arow1 < M;
    const float* Asrc0 = A + (size_t)(av0 ? arow0 : 0) * K + kc;
    const float* Asrc1 = A + (size_t)(av1 ? arow1 : 0) * K + kc;
    const float* Bsrc0 = Bm + (size_t)(n0 + r0) * K + kc;
    const float* Bsrc1 = Bm + (size_t)(n0 + r0 + 64) * K + kc;
    const unsigned sa = (unsigned)__cvta_generic_to_shared(Asm_) + (r0 * GSTR + kc) * 4;
    const unsigned sb = (unsigned)__cvta_generic_to_shared(Bsm_) + (r0 * GSTR + kc) * 4;
    const unsigned stg = GSTAGE_W * 4;
    const unsigned half = 64 * GSTR * 4;

    const int NIT = K >> 4;
    // prologue: stages 0..2
    #pragma unroll
    for (int s = 0; s < 3; s++) {
        int kb = s << 4;
        CPA16(sa + s * stg,        Asrc0 + kb, av0);
        CPA16(sa + s * stg + half, Asrc1 + kb, av1);
        CPA16(sb + s * stg,        Bsrc0 + kb, true);
        CPA16(sb + s * stg + half, Bsrc1 + kb, true);
        CP_COMMIT();
    }

    for (int it = 0; it < NIT; it++) {
        asm volatile("cp.async.wait_group 2;");
        __syncthreads();
        const unsigned* as = Asm_ + (it & 3) * GSTAGE_W;
        const unsigned* bs = Bsm_ + (it & 3) * GSTAGE_W;
        #pragma unroll
        for (int ks = 0; ks < 16; ks += 8) {
            unsigned af[4][4], bf[4][2];
            #pragma unroll
            for (int mt = 0; mt < 4; mt++) {
                int base = (wm * 64 + mt * 16 + g) * GSTR + ks + c;
                af[mt][0] = as[base];
                af[mt][1] = as[base + 8 * GSTR];
                af[mt][2] = as[base + 4];
                af[mt][3] = as[base + 8 * GSTR + 4];
            }
            #pragma unroll
            for (int nt = 0; nt < 4; nt++) {
                int base = (wn * 32 + nt * 8 + g) * GSTR + ks + c;
                bf[nt][0] = bs[base];
                bf[nt][1] = bs[base + 4];
            }
            #pragma unroll
            for (int mt = 0; mt < 4; mt++)
                #pragma unroll
                for (int nt = 0; nt < 4; nt++)
                    MMA_TF32(acc[mt][nt], af[mt], bf[nt]);
        }
        int kb = (it + 3) << 4;
        if (kb < K) {
            unsigned so = ((it + 3) & 3) * stg;
            CPA16(sa + so,        Asrc0 + kb, av0);
            CPA16(sa + so + half, Asrc1 + kb, av1);
            CPA16(sb + so,        Bsrc0 + kb, true);
            CPA16(sb + so + half, Bsrc1 + kb, true);
        }
        CP_COMMIT();
    }

    #pragma unroll
    for (int mt = 0; mt < 4; mt++) {
        #pragma unroll
        for (int hf = 0; hf < 2; hf++) {
            int r = m0 + wm * 64 + mt * 16 + g + hf * 8;
            if (r >= M) continue;
            #pragma unroll
            for (int nt = 0; nt < 4; nt++) {
                int col = n0 + wn * 32 + nt * 8 + 2 * c;
                float v0 = acc[mt][nt][hf * 2 + 0] + bias[col];
                float v1 = acc[mt][nt][hf * 2 + 1] + bias[col + 1];
                if (MODE == 1) { v0 = gelu_f(v0); v1 = gelu_f(v1); }
                if (MODE == 2) {
                    v0 += res[(size_t)r * N + col];
                    v1 += res[(size_t)r * N + col + 1];
                }
                if (RND) { v0 = rna(v0); v1 = rna(v1); }
                *(float2*)&Cm[(size_t)r * N + col] = make_float2(v0, v1);
            }
        }
    }
}

// ---------------- qk: attn = q*SCALE @ k^T via tf32 mma ----------------
#define QSTR 36

__global__ void __launch_bounds__(256) qk_mma(const float* __restrict__ qkv,
                                              float* __restrict__ attn)
{
    int bh = blockIdx.z;
    int bw = bh / NH, hh = bh % NH;
    int m0 = blockIdx.y * 128, n0 = blockIdx.x * 128;
    const float* qb = qkv + (size_t)bw * LW * 2304 + hh * HD;
    const float* kb_ = qb + 768;
    __shared__ __align__(16) unsigned Qs[128 * QSTR];
    __shared__ __align__(16) unsigned Ks[128 * QSTR];
    int t = threadIdx.x;
    int warp = t >> 5, lane = t & 31;
    int wm = warp >> 2, wn = warp & 3;
    int g = lane >> 2, c = lane & 3;
    float acc[4][4][4];
    #pragma unroll
    for (int i = 0; i < 4; i++)
        #pragma unroll
        for (int j = 0; j < 4; j++)
            #pragma unroll
            for (int q = 0; q < 4; q++) acc[i][j][q] = 0.f;

    #pragma unroll
    for (int k0 = 0; k0 < 64; k0 += 32) {
        if (k0) __syncthreads();
        #pragma unroll
        for (int q4 = 0; q4 < 4; q4++) {
            int id = t + q4 * 256;
            int row = id >> 3, lc = (id & 7) * 4;
            float4 qa = make_float4(0.f, 0.f, 0.f, 0.f), ka = qa;
            if (m0 + row < LW) qa = *(const float4*)(qb + (size_t)(m0 + row) * 2304 + k0 + lc);
            if (n0 + row < LW) ka = *(const float4*)(kb_ + (size_t)(n0 + row) * 2304 + k0 + lc);
            unsigned* qd = &Qs[row * QSTR + lc];
            qd[0] = f2u(qa.x * SCALE); qd[1] = f2u(qa.y * SCALE);
            qd[2] = f2u(qa.z * SCALE); qd[3] = f2u(qa.w * SCALE);
            unsigned* kd = &Ks[row * QSTR + lc];
            kd[0] = f2u(ka.x); kd[1] = f2u(ka.y); kd[2] = f2u(ka.z); kd[3] = f2u(ka.w);
        }
        __syncthreads();
        #pragma unroll
        for (int ks = 0; ks < 32; ks += 8) {
            unsigned af[4][4], bf[4][2];
            #pragma unroll
            for (int mt = 0; mt < 4; mt++) {
                int base = (wm * 64 + mt * 16 + g) * QSTR + ks + c;
                af[mt][0] = Qs[base];
                af[mt][1] = Qs[base + 8 * QSTR];
                af[mt][2] = Qs[base + 4];
                af[mt][3] = Qs[base + 8 * QSTR + 4];
            }
            #pragma unroll
            for (int nt = 0; nt < 4; nt++) {
                int base = (wn * 32 + nt * 8 + g) * QSTR + ks + c;
                bf[nt][0] = Ks[base];
                bf[nt][1] = Ks[base + 4];
            }
            #pragma unroll
            for (int mt = 0; mt < 4; mt++)
                #pragma unroll
                for (int nt = 0; nt < 4; nt++)
                    MMA_TF32(acc[mt][nt], af[mt], bf[nt]);
        }
    }

    float* ao = attn + (size_t)bh * ASLAB;
    #pragma unroll
    for (int mt = 0; mt < 4; mt++) {
        #pragma unroll
        for (int hf = 0; hf < 2; hf++) {
            int r = m0 + wm * 64 + mt * 16 + g + hf * 8;
            if (r >= LW) continue;
            #pragma unroll
            for (int nt = 0; nt < 4; nt++) {
                int col = n0 + wn * 32 + nt * 8 + 2 * c;
                if (col < APITCH)
                    *(float2*)&ao[(size_t)r * APITCH + col] =
                        make_float2(acc[mt][nt][hf * 2], acc[mt][nt][hf * 2 + 1]);
            }
        }
    }
}

// ---------------- fused rel-pos add + softmax (one block per attn row) ----------------
__global__ void __launch_bounds__(256) softmax_kernel(float* __restrict__ attn,
        const float* __restrict__ qkv, const float* __restrict__ rph,
        const float* __restrict__ rpw)
{
    int row = blockIdx.x;                 // 0 .. BH*LW-1
    int bh = row / LW, r = row % LW;
    int t = threadIdx.x;
    __shared__ float sq[64];
    __shared__ float srel[28];
    __shared__ float redm[8], reds[8];
    float* arow = attn + (size_t)bh * ASLAB + (size_t)r * APITCH;
    bool dorel = (r >= VPT);

    if (dorel) {
        int rr = r - VPT;
        int qi = rr / WS, qj = rr % WS;
        const float* qrow = qkv + (size_t)(bh / NH) * LW * 2304 + (size_t)r * 2304 + (bh % NH) * HD;
        if (t < 64) sq[t] = qrow[t];
        __syncthreads();
        if (t < 224) {
            int p = t >> 3, e = t & 7;
            int dir = p / 14, kk = p % 14;
            const float* rp = dir ? (rpw + (qj - kk + 13) * HD)
                                  : (rph + (qi - kk + 13) * HD);
            float s = 0.f;
            #pragma unroll
            for (int d = 0; d < 8; d++) s += sq[e * 8 + d] * rp[e * 8 + d];
            s += __shfl_down_sync(0xffffffffu, s, 4);
            s += __shfl_down_sync(0xffffffffu, s, 2);
            s += __shfl_down_sync(0xffffffffu, s, 1);
            if (e == 0) srel[p] = s;
        }
    }
    __syncthreads();

    float v = -1e30f;
    if (t < LW) {
        v = arow[t];
        if (dorel && t >= VPT) {
            int cc = t - VPT;
            v += srel[cc / 14] + srel[14 + cc % 14];
        }
    }
    float m = v;
    #pragma unroll
    for (int o = 16; o > 0; o >>= 1) m = fmaxf(m, __shfl_xor_sync(0xffffffffu, m, o));
    if ((t & 31) == 0) redm[t >> 5] = m;
    __syncthreads();
    m = redm[0];
    #pragma unroll
    for (int wi = 1; wi < 8; wi++) m = fmaxf(m, redm[wi]);

    float e = (t < LW) ? __expf(v - m) : 0.f;
    float s = e;
    #pragma unroll
    for (int o = 16; o > 0; o >>= 1) s += __shfl_xor_sync(0xffffffffu, s, o);
    if ((t & 31) == 0) reds[t >> 5] = s;
    __syncthreads();
    s = 0.f;
    #pragma unroll
    for (int wi = 0; wi < 8; wi++) s += reds[wi];

    if (t < APITCH) arow[t] = rna(e / s);   // tf32-exact P; pad cols exact 0
}

// ---------------- av: P(206x206,pitch208) @ V(206x64) via tf32 mma ----------------
#define VSTR 20

__global__ void __launch_bounds__(256) av_mma(const float* __restrict__ attn,
        const float* __restrict__ qkv, float* __restrict__ av)
{
    int bh = blockIdx.y;
    int m0 = blockIdx.x * 128;
    int bw = bh / NH, hh = bh % NH;
    const float* vb = qkv + (size_t)bw * LW * 2304 + hh * HD + 1536;
    const float* ab = attn + (size_t)bh * ASLAB;
    __shared__ __align__(16) unsigned Ps[128 * VSTR];
    __shared__ __align__(16) unsigned Vs[64 * VSTR];
    int t = threadIdx.x;
    int warp = t >> 5, lane = t & 31;
    int wm = warp >> 2, wn = warp & 3;     // warp tile 64x16
    int g = lane >> 2, c = lane & 3;
    float acc[4][2][4];
    #pragma unroll
    for (int i = 0; i < 4; i++)
        #pragma unroll
        for (int j = 0; j < 2; j++)
            #pragma unroll
            for (int q = 0; q < 4; q++) acc[i][j][q] = 0.f;

    for (int l0 = 0; l0 < APITCH; l0 += 16) {
        if (l0) __syncthreads();
        #pragma unroll
        for (int q2 = 0; q2 < 2; q2++) {
            int id = t + q2 * 256;
            int row = id >> 2, lc = (id & 3) * 4;
            float4 p = *(const float4*)(ab + (size_t)(m0 + row) * APITCH + l0 + lc);
            unsigned* pd = &Ps[row * VSTR + lc];
            pd[0] = f2u(p.x); pd[1] = f2u(p.y); pd[2] = f2u(p.z); pd[3] = f2u(p.w);
        }
        {
            int l = t >> 4, nc = (t & 15) * 4;
            float4 v = make_float4(0.f, 0.f, 0.f, 0.f);
            if (l0 + l < LW) v = *(const float4*)(vb + (size_t)(l0 + l) * 2304 + nc);
            Vs[(nc + 0) * VSTR + l] = f2u(v.x);
            Vs[(nc + 1) * VSTR + l] = f2u(v.y);
            Vs[(nc + 2) * VSTR + l] = f2u(v.z);
            Vs[(nc + 3) * VSTR + l] = f2u(v.w);
        }
        __syncthreads();
        #pragma unroll
        for (int ks = 0; ks < 16; ks += 8) {
            unsigned af[4][4], bf[2][2];
            #pragma unroll
            for (int mt = 0; mt < 4; mt++) {
                int base = (wm * 64 + mt * 16 + g) * VSTR + ks + c;
                af[mt][0] = Ps[base];
                af[mt][1] = Ps[base + 8 * VSTR];
                af[mt][2] = Ps[base + 4];
                af[mt][3] = Ps[base + 8 * VSTR + 4];
            }
            #pragma unroll
            for (int nt = 0; nt < 2; nt++) {
                int base = (wn * 16 + nt * 8 + g) * VSTR + ks + c;
                bf[nt][0] = Vs[base];
                bf[nt][1] = Vs[base + 4];
            }
            #pragma unroll
            for (int mt = 0; mt < 4; mt++)
                #pragma unroll
                for (int nt = 0; nt < 2; nt++)
                    MMA_TF32(acc[mt][nt], af[mt], bf[nt]);
        }
    }

    #pragma unroll
    for (int mt = 0; mt < 4; mt++) {
        #pragma unroll
        for (int hf = 0; hf < 2; hf++) {
            int m = m0 + wm * 64 + mt * 16 + g + hf * 8;
            if (m >= LW) continue;
            float* o = av + ((size_t)bw * LW + m) * C_ + hh * HD;
            #pragma unroll
            for (int nt = 0; nt < 2; nt++) {
                int col = wn * 16 + nt * 8 + 2 * c;
                *(float2*)&o[col] = make_float2(rna(acc[mt][nt][hf * 2]),
                                                rna(acc[mt][nt][hf * 2 + 1]));
            }
        }
    }
}

// ---------------- un-window + prompt-mean + residual ----------------
__global__ void combine_kernel(const float* __restrict__ x,
        const float* __restrict__ proj, float* __restrict__ x2)
{
    size_t idx = (size_t)blockIdx.x * 256 + threadIdx.x;
    if (idx >= (size_t)B_ * L_ * C_) return;
    int c = (int)(idx % C_);
    int rest = (int)(idx / C_);
    int tt = rest % L_;
    int b = rest / L_;
    float val;
    if (tt < VPT) {
        float s = 0.f;
        #pragma unroll
        for (int w = 0; w < NWIN; w++)
            s += proj[((size_t)(w * B_ + b) * LW + tt) * C_ + c];
        val = s * (1.f / NWIN);
    } else {
        int sp = tt - VPT;
        int h = sp >> 6, wc = sp & 63;
        int wh = h / WS,  i2 = h % WS;
        int ww = wc / WS, j2 = wc % WS;
        int bw = b * NWIN + wh * 5 + ww;
        int l  = VPT + i2 * WS + j2;
        val = proj[((size_t)bw * LW + l) * C_ + c];
    }
    x2[idx] = x[idx] + val;
}

// ---------------- launch ----------------
extern "C" void kernel_launch(void* const* d_in, const int* in_sizes, int n_in,
                              void* d_out, int out_size)
{
    const float* x      = (const float*)d_in[0];
    const float* ln1_w  = (const float*)d_in[1];
    const float* ln1_b  = (const float*)d_in[2];
    const float* qkv_w  = (const float*)d_in[3];
    const float* qkv_b  = (const float*)d_in[4];
    const float* proj_w = (const float*)d_in[5];
    const float* proj_b = (const float*)d_in[6];
    const float* rph    = (const float*)d_in[7];
    const float* rpw    = (const float*)d_in[8];
    const float* ln2_w  = (const float*)d_in[9];
    const float* ln2_b  = (const float*)d_in[10];
    const float* mlp_w1 = (const float*)d_in[11];
    const float* mlp_b1 = (const float*)d_in[12];
    const float* mlp_w2 = (const float*)d_in[13];
    const float* mlp_b2 = (const float*)d_in[14];
    float* out = (float*)d_out;

    float *xn, *tok, *qkv, *attn, *proj, *x2, *wbuf;
    cudaGetSymbolAddress((void**)&xn,   g_xn);
    cudaGetSymbolAddress((void**)&tok,  g_tok);
    cudaGetSymbolAddress((void**)&qkv,  g_qkv);
    cudaGetSymbolAddress((void**)&attn, g_attn);
    cudaGetSymbolAddress((void**)&proj, g_proj);
    cudaGetSymbolAddress((void**)&x2,   g_x2);
    cudaGetSymbolAddress((void**)&wbuf, g_w);

    cudaFuncSetAttribute(gemm_tf32<0,1>, cudaFuncAttributeMaxDynamicSharedMemorySize, GEMM_SMEM);
    cudaFuncSetAttribute(gemm_tf32<0,0>, cudaFuncAttributeMaxDynamicSharedMemorySize, GEMM_SMEM);
    cudaFuncSetAttribute(gemm_tf32<1,1>, cudaFuncAttributeMaxDynamicSharedMemorySize, GEMM_SMEM);
    cudaFuncSetAttribute(gemm_tf32<2,0>, cudaFuncAttributeMaxDynamicSharedMemorySize, GEMM_SMEM);

    // 0) pre-round weights to tf32 (RNA)
    round_w<<<(1769472 + 255) / 256, 256>>>(qkv_w,  wbuf + WOFF_QKV,  1769472);
    round_w<<<( 589824 + 255) / 256, 256>>>(proj_w, wbuf + WOFF_PROJ,  589824);
    round_w<<<(2359296 + 255) / 256, 256>>>(mlp_w1, wbuf + WOFF_W1,  2359296);
    round_w<<<(2359296 + 255) / 256, 256>>>(mlp_w2, wbuf + WOFF_W2,  2359296);

    // 1) LN1 (tf32-rounded out)
    ln_kernel<<<MX, 256>>>(x, ln1_w, ln1_b, xn);
    // 2) tok gather
    gather_tok<<<(int)(((size_t)BW * LW * C_ + 255) / 256), 256>>>(xn, tok);
    // 3) qkv = tok @ qkv_w^T + b (round out)
    gemm_tf32<0,1><<<dim3(2304 / 128, (MQ + 127) / 128), 256, GEMM_SMEM>>>(
        tok, wbuf + WOFF_QKV, qkv_b, nullptr, qkv, MQ, 2304, 768);
    // 4) attn = q*scale @ k^T
    qk_mma<<<dim3(2, 2, BH), 256>>>(qkv, attn);
    // 5) rel-pos + softmax (tf32-rounded P, pad cols zero)
    softmax_kernel<<<BH * LW, 256>>>(attn, qkv, rph, rpw);
    // 6) attn @ v -> (Bw,Lw,C) (round out)
    av_mma<<<dim3(2, BH), 256>>>(attn, qkv, tok);
    // 7) proj (final-path values: no rounding)
    gemm_tf32<0,0><<<dim3(768 / 128, (MQ + 127) / 128), 256, GEMM_SMEM>>>(
        tok, wbuf + WOFF_PROJ, proj_b, nullptr, proj, MQ, 768, 768);
    // 8) un-window + residual
    combine_kernel<<<(int)(((size_t)B_ * L_ * C_ + 255) / 256), 256>>>(x, proj, x2);
    // 9) LN2 (tf32-rounded out)
    ln_kernel<<<MX, 256>>>(x2, ln2_w, ln2_b, xn);
    // 10) MLP fc1 + gelu (round out)
    gemm_tf32<1,1><<<dim3(3072 / 128, (MX + 127) / 128), 256, GEMM_SMEM>>>(
        xn, wbuf + WOFF_W1, mlp_b1, nullptr, attn, MX, 3072, 768);
    // 11) MLP fc2 + residual -> out (no rounding)
    gemm_tf32<2,0><<<dim3(768 / 128, (MX + 127) / 128), 256, GEMM_SMEM>>>(
        attn, wbuf + WOFF_W2, mlp_b2, x2, out, MX, 768, 3072);
}